// round 14
// baseline (speedup 1.0000x reference)
#include <cuda_runtime.h>
#include <cuda_bf16.h>
#include <cstdint>

#define N_NODES 100000
#define N_EDGES 1200000
#define B_GR    512
#define HIDDIM  64
#define KSEL    3

#define SCAN_BLK 512
#define NBLK_SCAN ((N_NODES + SCAN_BLK - 1) / SCAN_BLK)   // 196

// ---------------- scratch (device globals; no allocation allowed) ----------------
__device__ int   g_odeg[N_NODES];
__device__ int   g_ideg[N_NODES];
__device__ int   g_start[N_NODES];     // CSR row start (by dst)
__device__ int   g_cursor[N_NODES];
__device__ int   g_blksum[NBLK_SCAN];
__device__ int   g_csr_src[N_EDGES];
__device__ float g_norm_s[N_NODES];
__device__ float g_norm_d[N_NODES];
__device__ __align__(256) float g_m[N_NODES * HIDDIM];
__device__ __align__(256) float g_h[N_NODES * HIDDIM];
__device__ float g_key[N_NODES];
__device__ int   g_sel[B_GR * KSEL];

// ---------------- CSR build ----------------
__global__ void k_zero_int() {
    int i = blockIdx.x * blockDim.x + threadIdx.x;
    if (i < N_NODES) { g_odeg[i] = 0; g_ideg[i] = 0; }
}

__global__ void k_deg(const int* __restrict__ src, const int* __restrict__ dst) {
    int e = blockIdx.x * blockDim.x + threadIdx.x;
    if (e < N_EDGES) {
        atomicAdd(&g_odeg[src[e]], 1);
        atomicAdd(&g_ideg[dst[e]], 1);
    }
}

// per-block inclusive scan of in_deg -> g_start, block totals -> g_blksum
__global__ void k_scan1() {
    __shared__ int wsum[16];
    int i = blockIdx.x * SCAN_BLK + threadIdx.x;
    int lane = threadIdx.x & 31, w = threadIdx.x >> 5;
    int v = (i < N_NODES) ? g_ideg[i] : 0;
    int x = v;
#pragma unroll
    for (int off = 1; off < 32; off <<= 1) {
        int n = __shfl_up_sync(0xffffffffu, x, off);
        if (lane >= off) x += n;
    }
    if (lane == 31) wsum[w] = x;
    __syncthreads();
    if (w == 0) {
        int s = (lane < 16) ? wsum[lane] : 0;
#pragma unroll
        for (int off = 1; off < 16; off <<= 1) {
            int n = __shfl_up_sync(0xffffffffu, s, off);
            if (lane >= off) s += n;
        }
        if (lane < 16) wsum[lane] = s;
    }
    __syncthreads();
    int add = (w > 0) ? wsum[w - 1] : 0;
    int incl = x + add;
    if (i < N_NODES) g_start[i] = incl;                 // inclusive, intra-block
    if (threadIdx.x == SCAN_BLK - 1) g_blksum[blockIdx.x] = incl;
}

// exclusive scan of 196 block sums (single block)
__global__ void k_scan2b() {
    __shared__ int sm[256];
    int t = threadIdx.x;
    int orig = (t < NBLK_SCAN) ? g_blksum[t] : 0;
    sm[t] = orig;
    __syncthreads();
#pragma unroll
    for (int off = 1; off < 256; off <<= 1) {
        int add = (t >= off) ? sm[t - off] : 0;
        __syncthreads();
        sm[t] += add;
        __syncthreads();
    }
    if (t < NBLK_SCAN) g_blksum[t] = sm[t] - orig;      // exclusive
}

// start = inclusive - deg + block offset; cursor = start; norms too (fused)
__global__ void k_scan3() {
    int i = blockIdx.x * blockDim.x + threadIdx.x;
    if (i < N_NODES) {
        int ideg = g_ideg[i];
        int s = g_start[i] - ideg + g_blksum[i / SCAN_BLK];
        g_start[i]  = s;
        g_cursor[i] = s;
        g_norm_s[i] = rsqrtf(fmaxf((float)g_odeg[i], 1.f));
        g_norm_d[i] = rsqrtf(fmaxf((float)ideg, 1.f));
    }
}

__global__ void k_fill(const int* __restrict__ src, const int* __restrict__ dst) {
    int e = blockIdx.x * blockDim.x + threadIdx.x;
    if (e < N_EDGES) {
        int pos = atomicAdd(&g_cursor[dst[e]], 1);
        g_csr_src[pos] = src[e];
    }
}

// ---------------- m = (h * norm_s) @ W  (exact fp32) ----------------
// 256 threads = 16 groups of 16 lanes; each group computes 8 rows,
// each lane owns 4 output columns (float4). W + H staged in smem.
// Group stride in Hsm padded to 520 floats -> cross-group bank-conflict free
// broadcasts in the inner loop.
__global__ void __launch_bounds__(256) k_gemm(const float* __restrict__ hin,
                                              const float* __restrict__ W,
                                              int use_gh) {
    __shared__ __align__(16) float Wsm[HIDDIM * HIDDIM];   // 16 KB
    __shared__ __align__(16) float Hsm[16 * 520];          // ~33 KB

    const float* srcp = use_gh ? (const float*)g_h : hin;

    int tid = threadIdx.x;
    for (int i = tid; i < HIDDIM * HIDDIM; i += 256) Wsm[i] = W[i];

    int g = tid >> 4, q = tid & 15;
    int base = blockIdx.x * 128 + g * 8;
    float* hb = &Hsm[g * 520];

    const float4* hin4 = (const float4*)srcp;
#pragma unroll
    for (int r = 0; r < 8; r++) {
        int row = base + r;
        float4 v = make_float4(0.f, 0.f, 0.f, 0.f);
        if (row < N_NODES) {
            float ns = g_norm_s[row];
            v = hin4[row * 16 + q];
            v.x *= ns; v.y *= ns; v.z *= ns; v.w *= ns;
        }
        ((float4*)&hb[r * 64])[q] = v;
    }
    __syncthreads();

    float4 acc[8];
#pragma unroll
    for (int r = 0; r < 8; r++) acc[r] = make_float4(0.f, 0.f, 0.f, 0.f);

    const float4* W4 = (const float4*)Wsm;
#pragma unroll 8
    for (int i = 0; i < HIDDIM; i++) {
        float4 w = W4[i * 16 + q];
#pragma unroll
        for (int r = 0; r < 8; r++) {
            float h = hb[r * 64 + i];               // smem broadcast (conflict-free)
            acc[r].x += h * w.x; acc[r].y += h * w.y;
            acc[r].z += h * w.z; acc[r].w += h * w.w;
        }
    }

    float4* m4 = (float4*)g_m;
#pragma unroll
    for (int r = 0; r < 8; r++) {
        int row = base + r;
        if (row < N_NODES) m4[row * 16 + q] = acc[r];
    }
}

// ---------------- gather: h[dst] = relu(norm_d * sum_{e:dst} m[src] + b) ----------------
// 16 lanes per dst node (lane owns float4 = 4 cols), 2 nodes per warp,
// 16 nodes per 256-thread block. N_NODES % 16 == 0 -> no ragged tail.
// Chunked 16-wide index prefetch + intra-half shuffle broadcast.
// do_key: also compute row max -> g_key.
__global__ void k_gather(const float* __restrict__ bvec, int do_key) {
    int tid  = threadIdx.x;
    int lane = tid & 31;
    int ql   = lane & 15;
    int warp = tid >> 5;
    int node = blockIdx.x * 16 + warp * 2 + ((lane >> 4) & 1);

    int start = g_start[node];
    int deg   = g_ideg[node];
    int degmax = max(deg, __shfl_xor_sync(0xffffffffu, deg, 16));

    const float4* m4 = (const float4*)g_m;
    float4 acc = make_float4(0.f, 0.f, 0.f, 0.f);

    for (int c = 0; c < degmax; c += 16) {
        int idx = c + ql;
        int s = (idx < deg) ? __ldg(&g_csr_src[start + idx]) : -1;
#pragma unroll 4
        for (int j = 0; j < 16; j++) {
            int sj = __shfl_sync(0xffffffffu, s, (lane & 16) | j);
            if (sj >= 0) {
                float4 v = __ldg(&m4[sj * 16 + ql]);
                acc.x += v.x; acc.y += v.y; acc.z += v.z; acc.w += v.w;
            }
        }
    }

    float nd = g_norm_d[node];
    float4 bb = __ldg(&((const float4*)bvec)[ql]);
    float4 h;
    h.x = fmaxf(acc.x * nd + bb.x, 0.f);
    h.y = fmaxf(acc.y * nd + bb.y, 0.f);
    h.z = fmaxf(acc.z * nd + bb.z, 0.f);
    h.w = fmaxf(acc.w * nd + bb.w, 0.f);
    ((float4*)g_h)[node * 16 + ql] = h;

    if (do_key) {
        float v = fmaxf(fmaxf(h.x, h.y), fmaxf(h.z, h.w));
#pragma unroll
        for (int off = 8; off > 0; off >>= 1)
            v = fmaxf(v, __shfl_xor_sync(0xffffffffu, v, off));
        if (ql == 0) g_key[node] = v;
    }
}

// ---------------- top-3 per graph (key desc, index asc tie-break) ----------------
__global__ void k_select(const int* __restrict__ gid) {
    if (threadIdx.x != 0) return;
    int g = blockIdx.x;
    int a = 0, b = N_NODES;
    while (a < b) { int mid = (a + b) >> 1; if (gid[mid] < g) a = mid + 1; else b = mid; }
    int lo = a;
    a = lo; b = N_NODES;
    while (a < b) { int mid = (a + b) >> 1; if (gid[mid] < g + 1) a = mid + 1; else b = mid; }
    int hi = a;

    float k0 = -1.f, k1 = -1.f, k2 = -1.f;
    int   i0 = -1,   i1 = -1,   i2 = -1;
    for (int idx = lo; idx < hi; idx++) {
        float kk = g_key[idx];
        if (kk > k0)      { k2 = k1; i2 = i1; k1 = k0; i1 = i0; k0 = kk; i0 = idx; }
        else if (kk > k1) { k2 = k1; i2 = i1; k1 = kk; i1 = idx; }
        else if (kk > k2) { k2 = kk; i2 = idx; }
    }
    g_sel[g * 3 + 0] = i0;
    g_sel[g * 3 + 1] = i1;
    g_sel[g * 3 + 2] = i2;
}

// ---------------- per-graph: sort 3 rows, conv-dot, classify (exact fp32) ----------------
__global__ void k_final(const float* __restrict__ cw, const float* __restrict__ cb,
                        const float* __restrict__ Wc, const float* __restrict__ bc,
                        float* __restrict__ out) {
    __shared__ float p[192];
    __shared__ float y[64];
    int g = blockIdx.x;
    int tid = threadIdx.x;
    int seg = tid / 64, t = tid % 64;

    int node = g_sel[g * 3 + seg];
    p[seg * 64 + t] = (node >= 0) ? g_h[node * 64 + t] : 0.f;
    __syncthreads();

    for (int k2 = 2; k2 <= 64; k2 <<= 1) {
        for (int j = k2 >> 1; j > 0; j >>= 1) {
            int ixj = t ^ j;
            if (ixj > t) {
                float a = p[seg * 64 + t], b = p[seg * 64 + ixj];
                bool up = ((t & k2) == 0);
                if ((a > b) == up) { p[seg * 64 + t] = b; p[seg * 64 + ixj] = a; }
            }
            __syncthreads();
        }
    }

    if (tid < 64) {
        float acc = cb[tid];
        const float* cwo = cw + tid * 192;
#pragma unroll 8
        for (int j = 0; j < 192; j++) acc += p[j] * cwo[j];
        y[tid] = fmaxf(acc, 0.f);
    }
    __syncthreads();

    if (tid < 10) {
        float acc = bc[tid];
#pragma unroll 8
        for (int o = 0; o < 64; o++) acc += y[o] * Wc[o * 10 + tid];
        out[g * 10 + tid] = acc;
    }
}

// ---------------- launch ----------------
extern "C" void kernel_launch(void* const* d_in, const int* in_sizes, int n_in,
                              void* d_out, int out_size) {
    const float* features = (const float*)d_in[0];
    const int*   esrc     = (const int*)  d_in[1];
    const int*   edst     = (const int*)  d_in[2];
    const int*   gid      = (const int*)  d_in[3];

    int base = (n_in >= 13) ? 5 : 4;
    const float* W1 = (const float*)d_in[base + 0];
    const float* b1 = (const float*)d_in[base + 1];
    const float* W2 = (const float*)d_in[base + 2];
    const float* b2 = (const float*)d_in[base + 3];
    const float* cw = (const float*)d_in[base + 4];
    const float* cb = (const float*)d_in[base + 5];
    const float* Wc = (const float*)d_in[base + 6];
    const float* bc = (const float*)d_in[base + 7];
    float* out = (float*)d_out;

    const int TB = 256;
    int gN  = (N_NODES + TB - 1) / TB;
    int gE  = (N_EDGES + TB - 1) / TB;
    int gGm = (N_NODES + 127) / 128;    // 128 rows per block
    int gGa = N_NODES / 16;             // 16 nodes per block (exact)

    // CSR build (shared by both layers) + norms
    k_zero_int<<<gN, TB>>>();
    k_deg<<<gE, TB>>>(esrc, edst);
    k_scan1<<<NBLK_SCAN, SCAN_BLK>>>();
    k_scan2b<<<1, 256>>>();
    k_scan3<<<gN, TB>>>();
    k_fill<<<gE, TB>>>(esrc, edst);

    // layer 1
    k_gemm<<<gGm, TB>>>(features, W1, 0);
    k_gather<<<gGa, TB>>>(b1, 0);

    // layer 2 (+ fused key)
    k_gemm<<<gGm, TB>>>(nullptr, W2, 1);
    k_gather<<<gGa, TB>>>(b2, 1);

    // sort-pool + conv + classifier
    k_select<<<B_GR, 32>>>(gid);
    k_final<<<B_GR, 192>>>(cw, cb, Wc, bc, out);
}

// round 15
// speedup vs baseline: 1.0380x; 1.0380x over previous
#include <cuda_runtime.h>
#include <cuda_bf16.h>
#include <cstdint>

#define N_NODES 100000
#define N_EDGES 1200000
#define B_GR    512
#define HIDDIM  64
#define KSEL    3

#define SCAN_BLK 512
#define NBLK_SCAN ((N_NODES + SCAN_BLK - 1) / SCAN_BLK)   // 196

// ---------------- scratch (device globals; no allocation allowed) ----------------
__device__ int   g_odeg[N_NODES];
__device__ int   g_ideg[N_NODES];
__device__ int   g_start[N_NODES];     // CSR row start (by dst)
__device__ int   g_cursor[N_NODES];
__device__ int   g_blksum[NBLK_SCAN];
__device__ int   g_csr_src[N_EDGES];
__device__ float g_norm_s[N_NODES];
__device__ float g_norm_d[N_NODES];
__device__ __align__(256) float g_m[N_NODES * HIDDIM];
__device__ __align__(256) float g_h[N_NODES * HIDDIM];
__device__ float g_key[N_NODES];
__device__ int   g_sel[B_GR * KSEL];

// ---------------- CSR build ----------------
__global__ void k_zero_int() {
    int i = blockIdx.x * blockDim.x + threadIdx.x;
    if (i < N_NODES) { g_odeg[i] = 0; g_ideg[i] = 0; }
}

__global__ void k_deg(const int* __restrict__ src, const int* __restrict__ dst) {
    int e = blockIdx.x * blockDim.x + threadIdx.x;
    if (e < N_EDGES) {
        atomicAdd(&g_odeg[src[e]], 1);
        atomicAdd(&g_ideg[dst[e]], 1);
    }
}

// per-block inclusive scan of in_deg -> g_start, block totals -> g_blksum
__global__ void k_scan1() {
    __shared__ int wsum[16];
    int i = blockIdx.x * SCAN_BLK + threadIdx.x;
    int lane = threadIdx.x & 31, w = threadIdx.x >> 5;
    int v = (i < N_NODES) ? g_ideg[i] : 0;
    int x = v;
#pragma unroll
    for (int off = 1; off < 32; off <<= 1) {
        int n = __shfl_up_sync(0xffffffffu, x, off);
        if (lane >= off) x += n;
    }
    if (lane == 31) wsum[w] = x;
    __syncthreads();
    if (w == 0) {
        int s = (lane < 16) ? wsum[lane] : 0;
#pragma unroll
        for (int off = 1; off < 16; off <<= 1) {
            int n = __shfl_up_sync(0xffffffffu, s, off);
            if (lane >= off) s += n;
        }
        if (lane < 16) wsum[lane] = s;
    }
    __syncthreads();
    int add = (w > 0) ? wsum[w - 1] : 0;
    int incl = x + add;
    if (i < N_NODES) g_start[i] = incl;                 // inclusive, intra-block
    if (threadIdx.x == SCAN_BLK - 1) g_blksum[blockIdx.x] = incl;
}

// exclusive scan of 196 block sums (single block)
__global__ void k_scan2b() {
    __shared__ int sm[256];
    int t = threadIdx.x;
    int orig = (t < NBLK_SCAN) ? g_blksum[t] : 0;
    sm[t] = orig;
    __syncthreads();
#pragma unroll
    for (int off = 1; off < 256; off <<= 1) {
        int add = (t >= off) ? sm[t - off] : 0;
        __syncthreads();
        sm[t] += add;
        __syncthreads();
    }
    if (t < NBLK_SCAN) g_blksum[t] = sm[t] - orig;      // exclusive
}

// start = inclusive - deg + block offset; cursor = start; norms too (fused)
__global__ void k_scan3() {
    int i = blockIdx.x * blockDim.x + threadIdx.x;
    if (i < N_NODES) {
        int ideg = g_ideg[i];
        int s = g_start[i] - ideg + g_blksum[i / SCAN_BLK];
        g_start[i]  = s;
        g_cursor[i] = s;
        g_norm_s[i] = rsqrtf(fmaxf((float)g_odeg[i], 1.f));
        g_norm_d[i] = rsqrtf(fmaxf((float)ideg, 1.f));
    }
}

__global__ void k_fill(const int* __restrict__ src, const int* __restrict__ dst) {
    int e = blockIdx.x * blockDim.x + threadIdx.x;
    if (e < N_EDGES) {
        int pos = atomicAdd(&g_cursor[dst[e]], 1);
        g_csr_src[pos] = src[e];
    }
}

// ---------------- m = (h * norm_s) @ W  (exact fp32) ----------------
// 256 threads = 16 groups of 16 lanes; each group computes 8 rows,
// each lane owns 4 output columns (float4). W + H staged in smem.
// Group stride in Hsm padded to 520 floats -> cross-group bank-conflict free
// broadcasts in the inner loop.
__global__ void __launch_bounds__(256) k_gemm(const float* __restrict__ hin,
                                              const float* __restrict__ W,
                                              int use_gh) {
    __shared__ __align__(16) float Wsm[HIDDIM * HIDDIM];   // 16 KB
    __shared__ __align__(16) float Hsm[16 * 520];          // ~33 KB

    const float* srcp = use_gh ? (const float*)g_h : hin;

    int tid = threadIdx.x;
    for (int i = tid; i < HIDDIM * HIDDIM; i += 256) Wsm[i] = W[i];

    int g = tid >> 4, q = tid & 15;
    int base = blockIdx.x * 128 + g * 8;
    float* hb = &Hsm[g * 520];

    const float4* hin4 = (const float4*)srcp;
#pragma unroll
    for (int r = 0; r < 8; r++) {
        int row = base + r;
        float4 v = make_float4(0.f, 0.f, 0.f, 0.f);
        if (row < N_NODES) {
            float ns = g_norm_s[row];
            v = hin4[row * 16 + q];
            v.x *= ns; v.y *= ns; v.z *= ns; v.w *= ns;
        }
        ((float4*)&hb[r * 64])[q] = v;
    }
    __syncthreads();

    float4 acc[8];
#pragma unroll
    for (int r = 0; r < 8; r++) acc[r] = make_float4(0.f, 0.f, 0.f, 0.f);

    const float4* W4 = (const float4*)Wsm;
#pragma unroll 8
    for (int i = 0; i < HIDDIM; i++) {
        float4 w = W4[i * 16 + q];
#pragma unroll
        for (int r = 0; r < 8; r++) {
            float h = hb[r * 64 + i];               // smem broadcast (conflict-free)
            acc[r].x += h * w.x; acc[r].y += h * w.y;
            acc[r].z += h * w.z; acc[r].w += h * w.w;
        }
    }

    float4* m4 = (float4*)g_m;
#pragma unroll
    for (int r = 0; r < 8; r++) {
        int row = base + r;
        if (row < N_NODES) m4[row * 16 + q] = acc[r];
    }
}

// ---------------- gather: h[dst] = relu(norm_d * sum_{e:dst} m[src] + b) ----------------
// 16 lanes per dst node (lane owns float4 = 4 cols), 2 nodes per warp,
// 16 nodes per 256-thread block. N_NODES % 16 == 0 -> no ragged tail.
// Chunked 16-wide index prefetch + intra-half shuffle broadcast.
// do_key: also compute row max -> g_key.
__global__ void k_gather(const float* __restrict__ bvec, int do_key) {
    int tid  = threadIdx.x;
    int lane = tid & 31;
    int ql   = lane & 15;
    int warp = tid >> 5;
    int node = blockIdx.x * 16 + warp * 2 + ((lane >> 4) & 1);

    int start = g_start[node];
    int deg   = g_ideg[node];
    int degmax = max(deg, __shfl_xor_sync(0xffffffffu, deg, 16));

    const float4* m4 = (const float4*)g_m;
    float4 acc = make_float4(0.f, 0.f, 0.f, 0.f);

    for (int c = 0; c < degmax; c += 16) {
        int idx = c + ql;
        int s = (idx < deg) ? __ldg(&g_csr_src[start + idx]) : -1;
#pragma unroll 4
        for (int j = 0; j < 16; j++) {
            int sj = __shfl_sync(0xffffffffu, s, (lane & 16) | j);
            if (sj >= 0) {
                float4 v = __ldg(&m4[sj * 16 + ql]);
                acc.x += v.x; acc.y += v.y; acc.z += v.z; acc.w += v.w;
            }
        }
    }

    float nd = g_norm_d[node];
    float4 bb = __ldg(&((const float4*)bvec)[ql]);
    float4 h;
    h.x = fmaxf(acc.x * nd + bb.x, 0.f);
    h.y = fmaxf(acc.y * nd + bb.y, 0.f);
    h.z = fmaxf(acc.z * nd + bb.z, 0.f);
    h.w = fmaxf(acc.w * nd + bb.w, 0.f);
    ((float4*)g_h)[node * 16 + ql] = h;

    if (do_key) {
        float v = fmaxf(fmaxf(h.x, h.y), fmaxf(h.z, h.w));
#pragma unroll
        for (int off = 8; off > 0; off >>= 1)
            v = fmaxf(v, __shfl_xor_sync(0xffffffffu, v, off));
        if (ql == 0) g_key[node] = v;
    }
}

// ---------------- top-3 per graph (key desc, index asc tie-break) ----------------
__global__ void k_select(const int* __restrict__ gid) {
    if (threadIdx.x != 0) return;
    int g = blockIdx.x;
    int a = 0, b = N_NODES;
    while (a < b) { int mid = (a + b) >> 1; if (gid[mid] < g) a = mid + 1; else b = mid; }
    int lo = a;
    a = lo; b = N_NODES;
    while (a < b) { int mid = (a + b) >> 1; if (gid[mid] < g + 1) a = mid + 1; else b = mid; }
    int hi = a;

    float k0 = -1.f, k1 = -1.f, k2 = -1.f;
    int   i0 = -1,   i1 = -1,   i2 = -1;
    for (int idx = lo; idx < hi; idx++) {
        float kk = g_key[idx];
        if (kk > k0)      { k2 = k1; i2 = i1; k1 = k0; i1 = i0; k0 = kk; i0 = idx; }
        else if (kk > k1) { k2 = k1; i2 = i1; k1 = kk; i1 = idx; }
        else if (kk > k2) { k2 = kk; i2 = idx; }
    }
    g_sel[g * 3 + 0] = i0;
    g_sel[g * 3 + 1] = i1;
    g_sel[g * 3 + 2] = i2;
}

// ---------------- per-graph: sort 3 rows, conv-dot, classify (exact fp32) ----------------
__global__ void k_final(const float* __restrict__ cw, const float* __restrict__ cb,
                        const float* __restrict__ Wc, const float* __restrict__ bc,
                        float* __restrict__ out) {
    __shared__ float p[192];
    __shared__ float y[64];
    int g = blockIdx.x;
    int tid = threadIdx.x;
    int seg = tid / 64, t = tid % 64;

    int node = g_sel[g * 3 + seg];
    p[seg * 64 + t] = (node >= 0) ? g_h[node * 64 + t] : 0.f;
    __syncthreads();

    for (int k2 = 2; k2 <= 64; k2 <<= 1) {
        for (int j = k2 >> 1; j > 0; j >>= 1) {
            int ixj = t ^ j;
            if (ixj > t) {
                float a = p[seg * 64 + t], b = p[seg * 64 + ixj];
                bool up = ((t & k2) == 0);
                if ((a > b) == up) { p[seg * 64 + t] = b; p[seg * 64 + ixj] = a; }
            }
            __syncthreads();
        }
    }

    if (tid < 64) {
        float acc = cb[tid];
        const float* cwo = cw + tid * 192;
#pragma unroll 8
        for (int j = 0; j < 192; j++) acc += p[j] * cwo[j];
        y[tid] = fmaxf(acc, 0.f);
    }
    __syncthreads();

    if (tid < 10) {
        float acc = bc[tid];
#pragma unroll 8
        for (int o = 0; o < 64; o++) acc += y[o] * Wc[o * 10 + tid];
        out[g * 10 + tid] = acc;
    }
}

// ---------------- launch ----------------
extern "C" void kernel_launch(void* const* d_in, const int* in_sizes, int n_in,
                              void* d_out, int out_size) {
    const float* features = (const float*)d_in[0];
    const int*   esrc     = (const int*)  d_in[1];
    const int*   edst     = (const int*)  d_in[2];
    const int*   gid      = (const int*)  d_in[3];

    int base = (n_in >= 13) ? 5 : 4;
    const float* W1 = (const float*)d_in[base + 0];
    const float* b1 = (const float*)d_in[base + 1];
    const float* W2 = (const float*)d_in[base + 2];
    const float* b2 = (const float*)d_in[base + 3];
    const float* cw = (const float*)d_in[base + 4];
    const float* cb = (const float*)d_in[base + 5];
    const float* Wc = (const float*)d_in[base + 6];
    const float* bc = (const float*)d_in[base + 7];
    float* out = (float*)d_out;

    const int TB = 256;
    int gN  = (N_NODES + TB - 1) / TB;
    int gE  = (N_EDGES + TB - 1) / TB;
    int gGm = (N_NODES + 127) / 128;    // 128 rows per block
    int gGa = N_NODES / 16;             // 16 nodes per block (exact)

    // CSR build (shared by both layers) + norms
    k_zero_int<<<gN, TB>>>();
    k_deg<<<gE, TB>>>(esrc, edst);
    k_scan1<<<NBLK_SCAN, SCAN_BLK>>>();
    k_scan2b<<<1, 256>>>();
    k_scan3<<<gN, TB>>>();
    k_fill<<<gE, TB>>>(esrc, edst);

    // layer 1
    k_gemm<<<gGm, TB>>>(features, W1, 0);
    k_gather<<<gGa, TB>>>(b1, 0);

    // layer 2 (+ fused key)
    k_gemm<<<gGm, TB>>>(nullptr, W2, 1);
    k_gather<<<gGa, TB>>>(b2, 1);

    // sort-pool + conv + classifier
    k_select<<<B_GR, 32>>>(gid);
    k_final<<<B_GR, 192>>>(cw, cb, Wc, bc, out);
}